// round 14
// baseline (speedup 1.0000x reference)
#include <cuda_runtime.h>
#include <math.h>
#include <stdint.h>

#define N_NODES 4096
#define N_HID   512
#define N_INF   512
#define N_S     10

// ---------------- scratch ----------------
__device__ float g_seqc[2][N_NODES * N_INF];
__device__ float g_Wc[2][N_HID * N_INF];
__device__ float g_fts[4][N_HID * N_NODES];          // ftsT: [h][node], tf32-rounded
__device__ float g_h[4][N_NODES * N_HID];
__device__ float g_Z[N_NODES * N_HID];
__device__ float g_Zt[N_HID * N_NODES];              // Z^T for fast G
__device__ float g_G[N_HID * N_HID];
__device__ float g_node_sq[(size_t)N_NODES * N_NODES];
__device__ float g_csum[2][N_HID];
__device__ float g_u[2][N_HID];
__device__ float g_rninv[N_NODES];
__device__ float g_cninv[N_HID];
__device__ float g_feat_loss;
__device__ float g_node_loss;

// ---------------- helpers ----------------
__device__ __forceinline__ unsigned f2tf32(float x) {
    unsigned r;
    asm("cvt.rna.tf32.f32 %0, %1;" : "=r"(r) : "f"(x));
    return r;
}

__device__ __forceinline__ void mma8(float (&c)[4], const unsigned (&a)[4],
                                     const unsigned (&b)[2]) {
    asm volatile(
        "mma.sync.aligned.m16n8k8.row.col.f32.tf32.tf32.f32 "
        "{%0,%1,%2,%3}, {%4,%5,%6,%7}, {%8,%9}, {%0,%1,%2,%3};\n"
        : "+f"(c[0]), "+f"(c[1]), "+f"(c[2]), "+f"(c[3])
        : "r"(a[0]), "r"(a[1]), "r"(a[2]), "r"(a[3]), "r"(b[0]), "r"(b[1]));
}

__device__ __forceinline__ void ldsm_x4(unsigned (&r)[4], uint32_t addr) {
    asm volatile("ldmatrix.sync.aligned.m8n8.x4.shared.b16 {%0,%1,%2,%3}, [%4];"
                 : "=r"(r[0]), "=r"(r[1]), "=r"(r[2]), "=r"(r[3]) : "r"(addr));
}

__device__ __forceinline__ void cpa16(uint32_t smem, const void* gmem) {
    asm volatile("cp.async.cg.shared.global [%0], [%1], 16;" :: "r"(smem), "l"(gmem));
}

// =========================================================================
// NT pipelined core (R8 config): C[128,128], 2 CTAs/SM, BK=32, 3 stages.
// =========================================================================
#define STG_BYTES 32768
#define STG_BOFF  16384
#define SMEM_TOTAL_G (3 * STG_BYTES)

__device__ __forceinline__ void nt_core(
    const float* __restrict__ A, int lda,
    const float* __restrict__ B, int ldb,
    int m0, int n0, int K, float (&acc)[4][4][4])
{
    extern __shared__ char smem[];
    const uint32_t sbase = (uint32_t)__cvta_generic_to_shared(smem);

    const int t = threadIdx.x;
    const int lane = t & 31, warp = t >> 5;
    const int wr = (warp & 1) * 64, wc = (warp >> 1) * 32;
    const int q = lane >> 3, rowin = lane & 7;
    const int qlo = q & 1, qhi = q >> 1;

    uint32_t aR[4], aSw[4], bR[2], bSw[2];
#pragma unroll
    for (int mt = 0; mt < 4; mt++) {
        int r = wr + mt * 16 + qlo * 8 + rowin;
        aR[mt] = r * 128; aSw[mt] = r & 7;
    }
#pragma unroll
    for (int np = 0; np < 2; np++) {
        int r = wc + (np * 2 + qhi) * 8 + rowin;
        bR[np] = r * 128; bSw[np] = r & 7;
    }

    const int KT = K >> 5;

    auto issue = [&](int kt, int buf) {
        const uint32_t sa = sbase + buf * STG_BYTES;
        const uint32_t sb = sa + STG_BOFF;
#pragma unroll
        for (int j = 0; j < 4; j++) {
            int c = t + j * 256;
            int r = c >> 3, c16 = c & 7;
            uint32_t sw = ((unsigned)(c16 ^ (r & 7))) << 4;
            cpa16(sa + r * 128 + sw, A + (size_t)(m0 + r) * lda + kt * 32 + c16 * 4);
            cpa16(sb + r * 128 + sw, B + (size_t)(n0 + r) * ldb + kt * 32 + c16 * 4);
        }
        asm volatile("cp.async.commit_group;");
    };

    issue(0, 0);
    issue(1, 1);

    for (int kt = 0; kt < KT; kt++) {
        if (kt + 1 < KT) { asm volatile("cp.async.wait_group 1;"); }
        else             { asm volatile("cp.async.wait_group 0;"); }
        __syncthreads();

        const uint32_t sa = sbase + (kt % 3) * STG_BYTES;
        const uint32_t sb = sa + STG_BOFF;
#pragma unroll
        for (int ks = 0; ks < 4; ks++) {
            unsigned af[4][4], bf[4][2];
#pragma unroll
            for (int mt = 0; mt < 4; mt++) {
                uint32_t c = ks * 2 + qhi;
                ldsm_x4(af[mt], sa + aR[mt] + ((c ^ aSw[mt]) << 4));
            }
#pragma unroll
            for (int np = 0; np < 2; np++) {
                unsigned r4[4];
                uint32_t c = ks * 2 + qlo;
                ldsm_x4(r4, sb + bR[np] + ((c ^ bSw[np]) << 4));
                bf[np * 2 + 0][0] = r4[0]; bf[np * 2 + 0][1] = r4[1];
                bf[np * 2 + 1][0] = r4[2]; bf[np * 2 + 1][1] = r4[3];
            }
#pragma unroll
            for (int mt = 0; mt < 4; mt++)
#pragma unroll
                for (int nt = 0; nt < 4; nt++)
                    mma8(acc[mt][nt], af[mt], bf[nt]);
        }
        if (kt + 2 < KT) issue(kt + 2, (kt + 2) % 3);
    }
}

#define ZERO_ACC4(acc)                             \
    _Pragma("unroll")                              \
    for (int mt = 0; mt < 4; mt++)                 \
        _Pragma("unroll")                          \
        for (int nt = 0; nt < 4; nt++)             \
            _Pragma("unroll")                      \
            for (int e = 0; e < 4; e++) acc[mt][nt][e] = 0.0f;

// ---------------- tf32 pre-convert + zero G + zero losses ----------------
#define CVT_SEQ  524288
#define CVT_W    65536
#define CVT_G    65536
#define CVT_TOT  (2 * CVT_SEQ + 2 * CVT_W + CVT_G)

__global__ void k_cvt_all(const float4* __restrict__ s1,  const float4* __restrict__ s2,
                          const float4* __restrict__ w1,  const float4* __restrict__ w2)
{
    long off = (long)blockIdx.x * 256 + threadIdx.x;
    if (off == 0) { g_feat_loss = 0.0f; g_node_loss = 0.0f; }
    const float4* src; float4* dst;
    if (off < CVT_SEQ)                   { src = s1;  dst = (float4*)g_seqc[0]; }
    else if ((off -= CVT_SEQ) < CVT_SEQ) { src = s2;  dst = (float4*)g_seqc[1]; }
    else if ((off -= CVT_SEQ) < CVT_W)   { src = w1;  dst = (float4*)g_Wc[0]; }
    else if ((off -= CVT_W) < CVT_W)     { src = w2;  dst = (float4*)g_Wc[1]; }
    else if ((off -= CVT_W) < CVT_G) {
        ((float4*)g_G)[off] = make_float4(0.f, 0.f, 0.f, 0.f);
        return;
    }
    else return;
    float4 v = src[off];
    v.x = __uint_as_float(f2tf32(v.x));
    v.y = __uint_as_float(f2tf32(v.y));
    v.z = __uint_as_float(f2tf32(v.z));
    v.w = __uint_as_float(f2tf32(v.w));
    dst[off] = v;
}

// ---------------- ftsT[z] = W[z] x seq[z]^T : M=512, N=4096, K=512 ----------------
__global__ __launch_bounds__(256, 2) void k_gemm_ftsT() {
    const int z = blockIdx.z;
    const float* A = g_Wc[z & 1];
    const float* B = g_seqc[z >> 1];
    float* __restrict__ C = g_fts[z];
    const int m0 = blockIdx.y * 128, n0 = blockIdx.x * 128;

    float acc[4][4][4];
    ZERO_ACC4(acc);
    nt_core(A, N_INF, B, N_INF, m0, n0, N_INF, acc);

    const int lane = threadIdx.x & 31, warp = threadIdx.x >> 5;
    const int g = lane >> 2, t4 = lane & 3;
    const int wr = (warp & 1) * 64, wc = (warp >> 1) * 32;
#pragma unroll
    for (int mt = 0; mt < 4; mt++)
#pragma unroll
        for (int nt = 0; nt < 4; nt++) {
            int row = m0 + wr + mt * 16 + g;
            int col = n0 + wc + nt * 8 + 2 * t4;
            float2 v01, v23;
            v01.x = __uint_as_float(f2tf32(acc[mt][nt][0]));
            v01.y = __uint_as_float(f2tf32(acc[mt][nt][1]));
            v23.x = __uint_as_float(f2tf32(acc[mt][nt][2]));
            v23.y = __uint_as_float(f2tf32(acc[mt][nt][3]));
            *(float2*)(C + (size_t)row * N_NODES + col) = v01;
            *(float2*)(C + (size_t)(row + 8) * N_NODES + col) = v23;
        }
}

// ---------------- h[z] = prelu(adj x ftsT^T + b): M=4096, N=512, K=4096 ------------
__global__ __launch_bounds__(256, 2) void k_gemm_prop(
    const float* __restrict__ adj, const float* __restrict__ diff,
    const float* __restrict__ b1,  const float* __restrict__ b2,
    const float* __restrict__ a1,  const float* __restrict__ a2)
{
    const int z = blockIdx.z;
    const float* A = (z & 1) ? diff : adj;
    const float* B = g_fts[z];
    const float* bias = (z & 1) ? b2 : b1;
    const float slope = (z & 1) ? a2[0] : a1[0];
    float* __restrict__ C = g_h[z];
    const int m0 = blockIdx.y * 128, n0 = blockIdx.x * 128;

    float acc[4][4][4];
    ZERO_ACC4(acc);
    nt_core(A, N_NODES, B, N_NODES, m0, n0, N_NODES, acc);

    const int lane = threadIdx.x & 31, warp = threadIdx.x >> 5;
    const int g = lane >> 2, t4 = lane & 3;
    const int wr = (warp & 1) * 64, wc = (warp >> 1) * 32;
#pragma unroll
    for (int mt = 0; mt < 4; mt++)
#pragma unroll
        for (int nt = 0; nt < 4; nt++) {
            int row = m0 + wr + mt * 16 + g;
            int col = n0 + wc + nt * 8 + 2 * t4;
            float b0 = bias[col], b1v = bias[col + 1];
            float2 v01, v23;
            v01.x = acc[mt][nt][0] + b0;  v01.y = acc[mt][nt][1] + b1v;
            v23.x = acc[mt][nt][2] + b0;  v23.y = acc[mt][nt][3] + b1v;
            v01.x = (v01.x >= 0.0f) ? v01.x : slope * v01.x;
            v01.y = (v01.y >= 0.0f) ? v01.y : slope * v01.y;
            v23.x = (v23.x >= 0.0f) ? v23.x : slope * v23.x;
            v23.y = (v23.y >= 0.0f) ? v23.y : slope * v23.y;
            *(float2*)(C + (size_t)row * N_HID + col) = v01;
            *(float2*)(C + (size_t)(row + 8) * N_HID + col) = v23;
        }
}

// ---------------- node_sq = (Zn Zn^T)^2, SYMMETRIC ----------------
__global__ __launch_bounds__(256, 2) void k_gemm_node() {
    const int bx = blockIdx.x, by = blockIdx.y;
    if (bx < by) return;
    const int m0 = by * 128, n0 = bx * 128;

    float acc[4][4][4];
    ZERO_ACC4(acc);
    nt_core(g_Z, N_HID, g_Z, N_HID, m0, n0, N_HID, acc);

    const int t = threadIdx.x;
    const int lane = t & 31, warp = t >> 5;
    const int g = lane >> 2, t4 = lane & 3;
    const int wr = (warp & 1) * 64, wc = (warp >> 1) * 32;

    extern __shared__ char smem[];
    float* smf = (float*)smem;
    const bool mirror = (bx != by);
    if (mirror) __syncthreads();

#pragma unroll
    for (int mt = 0; mt < 4; mt++) {
        int rowl = wr + mt * 16 + g;
        float ri0 = g_rninv[m0 + rowl], ri1 = g_rninv[m0 + rowl + 8];
#pragma unroll
        for (int nt = 0; nt < 4; nt++) {
            int coll = wc + nt * 8 + 2 * t4;
            float c0 = g_rninv[n0 + coll], c1 = g_rninv[n0 + coll + 1];
            float x0 = acc[mt][nt][0] * ri0 * c0;
            float x1 = acc[mt][nt][1] * ri0 * c1;
            float x2 = acc[mt][nt][2] * ri1 * c0;
            float x3 = acc[mt][nt][3] * ri1 * c1;
            float2 v01, v23;
            v01.x = x0 * x0; v01.y = x1 * x1;
            v23.x = x2 * x2; v23.y = x3 * x3;
            *(float2*)(g_node_sq + (size_t)(m0 + rowl) * N_NODES + n0 + coll) = v01;
            *(float2*)(g_node_sq + (size_t)(m0 + rowl + 8) * N_NODES + n0 + coll) = v23;
            if (mirror) {
                smf[(coll + 0) * 132 + rowl]     = v01.x;
                smf[(coll + 1) * 132 + rowl]     = v01.y;
                smf[(coll + 0) * 132 + rowl + 8] = v23.x;
                smf[(coll + 1) * 132 + rowl + 8] = v23.y;
            }
        }
    }
    if (mirror) {
        __syncthreads();
#pragma unroll
        for (int i = 0; i < 16; i++) {
            int idx4 = t + i * 256;
            int r2 = idx4 >> 5, c4 = idx4 & 31;
            float4 vv = *(float4*)(smf + r2 * 132 + c4 * 4);
            *(float4*)(g_node_sq + (size_t)(n0 + r2) * N_NODES + m0 + c4 * 4) = vv;
        }
    }
}

// ---------------- fused: Z = h1+h2 (tf32), rninv, and Z^T ----------------
// 128 blocks x 256 threads; each block: rows R0..R0+31, all 512 cols.
// Thread t: row r = t>>3, lane-in-row j = t&7, cols j*64..j*64+63.
// smem pitch 521 floats: bank = (9r + c) % 32, gcd(9,32)=1 -> conflict-free
// column reads for the Zt write phase.
__global__ __launch_bounds__(256) void k_compute_Zt() {
    __shared__ float sz[32 * 521];
    const int t = threadIdx.x;
    const int r = t >> 3, j = t & 7;
    const int R0 = blockIdx.x * 32;
    const size_t rowoff = (size_t)(R0 + r) * N_HID;

    float ss = 0.0f;
#pragma unroll
    for (int i = 0; i < 16; i++) {
        int c = j * 64 + i * 4;
        float4 a = *(const float4*)(g_h[0] + rowoff + c);
        float4 b = *(const float4*)(g_h[1] + rowoff + c);
        float4 z;
        z.x = __uint_as_float(f2tf32(a.x + b.x));
        z.y = __uint_as_float(f2tf32(a.y + b.y));
        z.z = __uint_as_float(f2tf32(a.z + b.z));
        z.w = __uint_as_float(f2tf32(a.w + b.w));
        *(float4*)(g_Z + rowoff + c) = z;
        sz[r * 521 + c + 0] = z.x;
        sz[r * 521 + c + 1] = z.y;
        sz[r * 521 + c + 2] = z.z;
        sz[r * 521 + c + 3] = z.w;
        ss += z.x * z.x + z.y * z.y + z.z * z.z + z.w * z.w;
    }
    // reduce over the 8 lanes of this row (lanes j = bits 0..2 of lane id)
#pragma unroll
    for (int d = 4; d > 0; d >>= 1) ss += __shfl_xor_sync(0xFFFFFFFFu, ss, d);
    if (j == 0) g_rninv[R0 + r] = 1.0f / fmaxf(sqrtf(ss), 1e-12f);
    __syncthreads();

    // Zt write: thread t handles cols c = 2t, 2t+1; 32 consecutive rows each.
#pragma unroll
    for (int cc = 0; cc < 2; cc++) {
        int c = t * 2 + cc;
        float4 v;
        float* dst = g_Zt + (size_t)c * N_NODES + R0;
#pragma unroll
        for (int rb = 0; rb < 8; rb++) {
            v.x = sz[(rb * 4 + 0) * 521 + c];
            v.y = sz[(rb * 4 + 1) * 521 + c];
            v.z = sz[(rb * 4 + 2) * 521 + c];
            v.w = sz[(rb * 4 + 3) * 521 + c];
            *(float4*)(dst + rb * 4) = v;
        }
    }
}

// ---------------- column reductions ----------------
__global__ void k_col_reduce() {
    const int mode = blockIdx.y;
    const int tx = threadIdx.x & 31;
    const int ty = threadIdx.x >> 5;
    const int col = blockIdx.x * 32 + tx;
    const float* __restrict__ src = (mode == 0) ? g_h[0] : (mode == 1) ? g_h[1] : g_Z;
    float s = 0.0f;
    for (int r = ty; r < N_NODES; r += 8) {
        float v = src[(size_t)r * N_HID + col];
        s += (mode == 2) ? v * v : v;
    }
    __shared__ float sm[8][32];
    sm[ty][tx] = s;
    __syncthreads();
    if (ty == 0) {
        float tot = 0.0f;
#pragma unroll
        for (int k = 0; k < 8; k++) tot += sm[k][tx];
        if (mode == 2) g_cninv[col] = 1.0f / fmaxf(sqrtf(tot), 1e-12f);
        else g_csum[mode][col] = tot;
    }
}

// ---------------- u = Wd @ sigmoid(colmean) ----------------
__global__ void k_compute_u(const float* __restrict__ Wd) {
    __shared__ float c1s[512], c2s[512];
    const int h = threadIdx.x;
    c1s[h] = 1.0f / (1.0f + expf(-g_csum[0][h] * (1.0f / 4096.0f)));
    c2s[h] = 1.0f / (1.0f + expf(-g_csum[1][h] * (1.0f / 4096.0f)));
    __syncthreads();
    float u1 = 0.0f, u2 = 0.0f;
    const float4* Wrow = reinterpret_cast<const float4*>(Wd + (size_t)h * N_HID);
#pragma unroll 4
    for (int k4 = 0; k4 < 128; k4++) {
        float4 w = Wrow[k4];
        int k = k4 * 4;
        u1 += w.x * c1s[k] + w.y * c1s[k + 1] + w.z * c1s[k + 2] + w.w * c1s[k + 3];
        u2 += w.x * c2s[k] + w.y * c2s[k + 1] + w.z * c2s[k + 2] + w.w * c2s[k + 3];
    }
    g_u[0][h] = u1;
    g_u[1][h] = u2;
}

// ---------------- ret ----------------
__global__ void k_ret(const float* __restrict__ bd, float* __restrict__ out) {
    const int q = blockIdx.y;
    const int n = blockIdx.x * 8 + (threadIdx.x >> 5);
    const int lane = threadIdx.x & 31;
    const float* __restrict__ h = (q == 0) ? g_h[1] : (q == 1) ? g_h[0]
                                : (q == 2) ? g_h[3] : g_h[2];
    const float* __restrict__ u = (q == 0 || q == 2) ? g_u[0] : g_u[1];
    float s = 0.0f;
    for (int k = lane; k < N_HID; k += 32)
        s += h[(size_t)n * N_HID + k] * u[k];
#pragma unroll
    for (int o = 16; o > 0; o >>= 1) s += __shfl_down_sync(0xFFFFFFFFu, s, o);
    if (lane == 0) out[q * N_NODES + n] = s + bd[0];
}

// ---------------- G = Z^T Z via fast NT core on Zt (split-K=8) ----------------
__global__ __launch_bounds__(256, 2) void k_gemm_G() {
    const int m0 = blockIdx.y * 128, n0 = blockIdx.x * 128;
    const float* Zt = g_Zt + (size_t)blockIdx.z * 512;

    float acc[4][4][4];
    ZERO_ACC4(acc);
    nt_core(Zt, N_NODES, Zt, N_NODES, m0, n0, 512, acc);

    const int lane = threadIdx.x & 31, warp = threadIdx.x >> 5;
    const int g = lane >> 2, t4 = lane & 3;
    const int wr = (warp & 1) * 64, wc = (warp >> 1) * 32;
#pragma unroll
    for (int mt = 0; mt < 4; mt++)
#pragma unroll
        for (int nt = 0; nt < 4; nt++)
#pragma unroll
            for (int e = 0; e < 4; e++) {
                int row = m0 + wr + mt * 16 + g + (e >> 1) * 8;
                int col = n0 + wc + nt * 8 + 2 * t4 + (e & 1);
                atomicAdd(&g_G[(size_t)row * N_HID + col], acc[mt][nt][e]);
            }
}

// ---------------- feat loss: 64-thread register bitonic over 512 ----------------
__global__ __launch_bounds__(64) void k_feat_loss(const int* __restrict__ feat_index) {
    const int h = blockIdx.x;
    const int t = threadIdx.x;
    __shared__ float sm[512];
    __shared__ float s_diag;

    const float ch = g_cninv[h];
    float v[8];
    {
        const float4* Gr = reinterpret_cast<const float4*>(g_G + (size_t)h * N_HID) + t * 2;
        float4 a = Gr[0], b = Gr[1];
        int base = t * 8;
        float f;
        f = a.x * ch * g_cninv[base + 0]; v[0] = f * f;
        f = a.y * ch * g_cninv[base + 1]; v[1] = f * f;
        f = a.z * ch * g_cninv[base + 2]; v[2] = f * f;
        f = a.w * ch * g_cninv[base + 3]; v[3] = f * f;
        f = b.x * ch * g_cninv[base + 4]; v[4] = f * f;
        f = b.y * ch * g_cninv[base + 5]; v[5] = f * f;
        f = b.z * ch * g_cninv[base + 6]; v[6] = f * f;
        f = b.w * ch * g_cninv[base + 7]; v[7] = f * f;
    }
    if (t == (h >> 3)) s_diag = v[h & 7];
    __syncthreads();
    const float diag = s_diag;

    for (int kk = 2; kk <= 512; kk <<= 1) {
        for (int j = kk >> 1; j > 0; j >>= 1) {
            if (j >= 256) {
                const int d = j >> 3;
                const bool lower = (t & d) == 0;
                const bool up = ((t & (kk >> 3)) == 0);
                const bool keepmin = (up == lower);
                __syncthreads();
#pragma unroll
                for (int e = 0; e < 8; e++) sm[t * 8 + e] = v[e];
                __syncthreads();
#pragma unroll
                for (int e = 0; e < 8; e++) {
                    float o = sm[(t ^ d) * 8 + e];
                    v[e] = keepmin ? fminf(v[e], o) : fmaxf(v[e], o);
                }
            } else if (j >= 8) {
                const int d = j >> 3;
                const bool lower = (t & d) == 0;
                const bool up = ((t & (kk >> 3)) == 0);
                const bool keepmin = (up == lower);
#pragma unroll
                for (int e = 0; e < 8; e++) {
                    float o = __shfl_xor_sync(0xFFFFFFFFu, v[e], d);
                    v[e] = keepmin ? fminf(v[e], o) : fmaxf(v[e], o);
                }
            } else {
#pragma unroll
                for (int e = 0; e < 8; e++) {
                    if ((e & j) == 0) {
                        int p = e | j;
                        bool up = ((((t << 3) | e) & kk) == 0);
                        float a = v[e], b = v[p];
                        float lo = fminf(a, b), hi = fmaxf(a, b);
                        v[e] = up ? lo : hi;
                        v[p] = up ? hi : lo;
                    }
                }
            }
        }
    }
    __syncthreads();
#pragma unroll
    for (int e = 0; e < 8; e++) sm[t * 8 + e] = v[e];
    __syncthreads();
    if (t == 0) {
        float neg = 0.0f;
#pragma unroll
        for (int s = 0; s < N_S; s++) neg += expf(2.0f * sm[feat_index[s]]);
        float pos = expf(2.0f * diag);
        atomicAdd(&g_feat_loss, (logf(neg) - logf(pos)) * (1.0f / 512.0f));
    }
}

// ---------------- node loss: register/shuffle bitonic ----------------
__global__ __launch_bounds__(512) void k_node_sel(const float* __restrict__ adj_label,
                                                  const int* __restrict__ node_index) {
    const int i = blockIdx.x;
    const int t = threadIdx.x;
    __shared__ float sm[4096];
    __shared__ float red[16];
    const float* __restrict__ trow = g_node_sq + (size_t)i * N_NODES;
    const float* __restrict__ lrow = adj_label + (size_t)i * N_NODES;

    float v[8];
    float pos = 0.0f;
    {
        const float4* t4p = reinterpret_cast<const float4*>(trow) + t * 2;
        const float4* l4p = reinterpret_cast<const float4*>(lrow) + t * 2;
        float4 a = t4p[0], b = t4p[1];
        float4 la = l4p[0], lb = l4p[1];
        v[0] = a.x; v[1] = a.y; v[2] = a.z; v[3] = a.w;
        v[4] = b.x; v[5] = b.y; v[6] = b.z; v[7] = b.w;
        pos += __expf(2.0f * a.x) * la.x + __expf(2.0f * a.y) * la.y
             + __expf(2.0f * a.z) * la.z + __expf(2.0f * a.w) * la.w
             + __expf(2.0f * b.x) * lb.x + __expf(2.0f * b.y) * lb.y
             + __expf(2.0f * b.z) * lb.z + __expf(2.0f * b.w) * lb.w;
    }
    // warp reduce + one smem round
#pragma unroll
    for (int o = 16; o > 0; o >>= 1) pos += __shfl_xor_sync(0xFFFFFFFFu, pos, o);
    if ((t & 31) == 0) red[t >> 5] = pos;
    __syncthreads();
    float posSum;
    {
        float rsum = red[t & 15];
        // every thread computes total (16 values) via shuffle in first warp pattern
        // simpler: all threads sum 16 smem values (broadcast reads, no conflict)
        rsum = 0.0f;
#pragma unroll
        for (int w = 0; w < 16; w++) rsum += red[w];
        posSum = rsum;
    }

    for (int kk = 2; kk <= 4096; kk <<= 1) {
        for (int j = kk >> 1; j > 0; j >>= 1) {
            if (j >= 256) {
                const int d = j >> 3;
                const bool lower = (t & d) == 0;
                const bool up = ((t & (kk >> 3)) == 0);
                const bool keepmin = (up == lower);
                __syncthreads();
#pragma unroll
                for (int e = 0; e < 8; e++) sm[t * 8 + e] = v[e];
                __syncthreads();
#pragma unroll
                for (int e = 0; e < 8; e++) {
                    float o = sm[(t ^ d) * 8 + e];
                    v[e] = keepmin ? fminf(v[e], o) : fmaxf(v[e], o);
                }
            } else if (j >= 8) {
                const int d = j >> 3;
                const bool lower = (t & d) == 0;
                const bool up = ((t & (kk >> 3)) == 0);
                const bool keepmin = (up == lower);
#pragma unroll
                for (int e = 0; e < 8; e++) {
                    float o = __shfl_xor_sync(0xFFFFFFFFu, v[e], d);
                    v[e] = keepmin ? fminf(v[e], o) : fmaxf(v[e], o);
                }
            } else {
#pragma unroll
                for (int e = 0; e < 8; e++) {
                    if ((e & j) == 0) {
                        int p = e | j;
                        bool up = ((((t << 3) | e) & kk) == 0);
                        float a = v[e], b = v[p];
                        float lo = fminf(a, b), hi = fmaxf(a, b);
                        v[e] = up ? lo : hi;
                        v[p] = up ? hi : lo;
                    }
                }
            }
        }
    }
    __syncthreads();
#pragma unroll
    for (int e = 0; e < 8; e++) sm[t * 8 + e] = v[e];
    __syncthreads();
    if (t == 0) {
        float neg = 0.0f;
#pragma unroll
        for (int s = 0; s < N_S; s++) neg += __expf(2.0f * sm[node_index[s]]);
        atomicAdd(&g_node_loss, (logf(neg) - logf(posSum)) * (1.0f / 4096.0f));
    }
}

// ---------------- finalize ----------------
__global__ void k_finalize(float* __restrict__ out) {
    out[4 * N_NODES + 0] = g_feat_loss;
    out[4 * N_NODES + 1] = g_node_loss;
}

// ---------------- launch ----------------
extern "C" void kernel_launch(void* const* d_in, const int* in_sizes, int n_in,
                              void* d_out, int out_size) {
    const float* seq1      = (const float*)d_in[0];
    const float* seq2      = (const float*)d_in[1];
    const float* adj       = (const float*)d_in[2];
    const float* diff      = (const float*)d_in[3];
    const float* adj_label = (const float*)d_in[4];
    const int*   feat_idx  = (const int*)d_in[5];
    const int*   node_idx  = (const int*)d_in[6];
    const float* b1        = (const float*)d_in[8];
    const float* a1        = (const float*)d_in[9];
    const float* b2        = (const float*)d_in[11];
    const float* a2        = (const float*)d_in[12];
    const float* Wd        = (const float*)d_in[13];
    const float* bd        = (const float*)d_in[14];
    float* out = (float*)d_out;

    cudaFuncSetAttribute(k_gemm_ftsT, cudaFuncAttributeMaxDynamicSharedMemorySize, SMEM_TOTAL_G);
    cudaFuncSetAttribute(k_gemm_prop, cudaFuncAttributeMaxDynamicSharedMemorySize, SMEM_TOTAL_G);
    cudaFuncSetAttribute(k_gemm_node, cudaFuncAttributeMaxDynamicSharedMemorySize, SMEM_TOTAL_G);
    cudaFuncSetAttribute(k_gemm_G,    cudaFuncAttributeMaxDynamicSharedMemorySize, SMEM_TOTAL_G);

    k_cvt_all<<<(CVT_TOT + 255) / 256, 256>>>(
        (const float4*)seq1, (const float4*)seq2,
        (const float4*)d_in[7], (const float4*)d_in[10]);
    k_gemm_ftsT<<<dim3(32, 4, 4), 256, SMEM_TOTAL_G>>>();
    k_gemm_prop<<<dim3(4, 32, 4), 256, SMEM_TOTAL_G>>>(adj, diff, b1, b2, a1, a2);
    k_compute_Zt<<<128, 256>>>();
    k_col_reduce<<<dim3(16, 3), 256>>>();
    k_compute_u<<<1, 512>>>(Wd);
    k_ret<<<dim3(512, 4), 256>>>(bd, out);
    k_gemm_G<<<dim3(4, 4, 8), 256, SMEM_TOTAL_G>>>();
    k_feat_loss<<<512, 64>>>(feat_idx);
    k_gemm_node<<<dim3(32, 32), 256, SMEM_TOTAL_G>>>();
    k_node_sel<<<N_NODES, 512>>>(adj_label, node_idx);
    k_finalize<<<1, 1>>>(out);
}

// round 15
// speedup vs baseline: 1.0494x; 1.0494x over previous
#include <cuda_runtime.h>
#include <math.h>
#include <stdint.h>

#define N_NODES 4096
#define N_HID   512
#define N_INF   512
#define N_S     10

// ---------------- scratch ----------------
__device__ float g_seqc[2][N_NODES * N_INF];
__device__ float g_Wc[2][N_HID * N_INF];
__device__ float g_fts[4][N_HID * N_NODES];
__device__ float g_h[4][N_NODES * N_HID];
__device__ float g_Z[N_NODES * N_HID];
__device__ float g_Zt[N_HID * N_NODES];
__device__ float g_G[N_HID * N_HID];
__device__ float g_node_sq[(size_t)N_NODES * N_NODES];
__device__ float g_csum[2][N_HID];
__device__ float g_u[2][N_HID];
__device__ float g_rninv[N_NODES];
__device__ float g_cninv[N_HID];
__device__ float g_feat_loss;
__device__ float g_node_loss;

// ---------------- helpers ----------------
__device__ __forceinline__ unsigned f2tf32(float x) {
    unsigned r;
    asm("cvt.rna.tf32.f32 %0, %1;" : "=r"(r) : "f"(x));
    return r;
}

__device__ __forceinline__ void mma8(float (&c)[4], const unsigned (&a)[4],
                                     const unsigned (&b)[2]) {
    asm volatile(
        "mma.sync.aligned.m16n8k8.row.col.f32.tf32.tf32.f32 "
        "{%0,%1,%2,%3}, {%4,%5,%6,%7}, {%8,%9}, {%0,%1,%2,%3};\n"
        : "+f"(c[0]), "+f"(c[1]), "+f"(c[2]), "+f"(c[3])
        : "r"(a[0]), "r"(a[1]), "r"(a[2]), "r"(a[3]), "r"(b[0]), "r"(b[1]));
}

__device__ __forceinline__ void ldsm_x4(unsigned (&r)[4], uint32_t addr) {
    asm volatile("ldmatrix.sync.aligned.m8n8.x4.shared.b16 {%0,%1,%2,%3}, [%4];"
                 : "=r"(r[0]), "=r"(r[1]), "=r"(r[2]), "=r"(r[3]) : "r"(addr));
}

__device__ __forceinline__ void cpa16(uint32_t smem, const void* gmem) {
    asm volatile("cp.async.cg.shared.global [%0], [%1], 16;" :: "r"(smem), "l"(gmem));
}

// =========================================================================
// NT pipelined core (R8 config): C[128,128], 2 CTAs/SM, BK=32, 3 stages.
// =========================================================================
#define STG_BYTES 32768
#define STG_BOFF  16384
#define SMEM_TOTAL_G (3 * STG_BYTES)

__device__ __forceinline__ void nt_core(
    const float* __restrict__ A, int lda,
    const float* __restrict__ B, int ldb,
    int m0, int n0, int K, float (&acc)[4][4][4])
{
    extern __shared__ char smem[];
    const uint32_t sbase = (uint32_t)__cvta_generic_to_shared(smem);

    const int t = threadIdx.x;
    const int lane = t & 31, warp = t >> 5;
    const int wr = (warp & 1) * 64, wc = (warp >> 1) * 32;
    const int q = lane >> 3, rowin = lane & 7;
    const int qlo = q & 1, qhi = q >> 1;

    uint32_t aR[4], aSw[4], bR[2], bSw[2];
#pragma unroll
    for (int mt = 0; mt < 4; mt++) {
        int r = wr + mt * 16 + qlo * 8 + rowin;
        aR[mt] = r * 128; aSw[mt] = r & 7;
    }
#pragma unroll
    for (int np = 0; np < 2; np++) {
        int r = wc + (np * 2 + qhi) * 8 + rowin;
        bR[np] = r * 128; bSw[np] = r & 7;
    }

    const int KT = K >> 5;

    auto issue = [&](int kt, int buf) {
        const uint32_t sa = sbase + buf * STG_BYTES;
        const uint32_t sb = sa + STG_BOFF;
#pragma unroll
        for (int j = 0; j < 4; j++) {
            int c = t + j * 256;
            int r = c >> 3, c16 = c & 7;
            uint32_t sw = ((unsigned)(c16 ^ (r & 7))) << 4;
            cpa16(sa + r * 128 + sw, A + (size_t)(m0 + r) * lda + kt * 32 + c16 * 4);
            cpa16(sb + r * 128 + sw, B + (size_t)(n0 + r) * ldb + kt * 32 + c16 * 4);
        }
        asm volatile("cp.async.commit_group;");
    };

    issue(0, 0);
    issue(1, 1);

    for (int kt = 0; kt < KT; kt++) {
        if (kt + 1 < KT) { asm volatile("cp.async.wait_group 1;"); }
        else             { asm volatile("cp.async.wait_group 0;"); }
        __syncthreads();

        const uint32_t sa = sbase + (kt % 3) * STG_BYTES;
        const uint32_t sb = sa + STG_BOFF;
#pragma unroll
        for (int ks = 0; ks < 4; ks++) {
            unsigned af[4][4], bf[4][2];
#pragma unroll
            for (int mt = 0; mt < 4; mt++) {
                uint32_t c = ks * 2 + qhi;
                ldsm_x4(af[mt], sa + aR[mt] + ((c ^ aSw[mt]) << 4));
            }
#pragma unroll
            for (int np = 0; np < 2; np++) {
                unsigned r4[4];
                uint32_t c = ks * 2 + qlo;
                ldsm_x4(r4, sb + bR[np] + ((c ^ bSw[np]) << 4));
                bf[np * 2 + 0][0] = r4[0]; bf[np * 2 + 0][1] = r4[1];
                bf[np * 2 + 1][0] = r4[2]; bf[np * 2 + 1][1] = r4[3];
            }
#pragma unroll
            for (int mt = 0; mt < 4; mt++)
#pragma unroll
                for (int nt = 0; nt < 4; nt++)
                    mma8(acc[mt][nt], af[mt], bf[nt]);
        }
        if (kt + 2 < KT) issue(kt + 2, (kt + 2) % 3);
    }
}

#define ZERO_ACC4(acc)                             \
    _Pragma("unroll")                              \
    for (int mt = 0; mt < 4; mt++)                 \
        _Pragma("unroll")                          \
        for (int nt = 0; nt < 4; nt++)             \
            _Pragma("unroll")                      \
            for (int e = 0; e < 4; e++) acc[mt][nt][e] = 0.0f;

// ---------------- tf32 pre-convert + zero G + zero losses ----------------
#define CVT_SEQ  524288
#define CVT_W    65536
#define CVT_G    65536
#define CVT_TOT  (2 * CVT_SEQ + 2 * CVT_W + CVT_G)

__global__ void k_cvt_all(const float4* __restrict__ s1,  const float4* __restrict__ s2,
                          const float4* __restrict__ w1,  const float4* __restrict__ w2)
{
    long off = (long)blockIdx.x * 256 + threadIdx.x;
    if (off == 0) { g_feat_loss = 0.0f; g_node_loss = 0.0f; }
    const float4* src; float4* dst;
    if (off < CVT_SEQ)                   { src = s1;  dst = (float4*)g_seqc[0]; }
    else if ((off -= CVT_SEQ) < CVT_SEQ) { src = s2;  dst = (float4*)g_seqc[1]; }
    else if ((off -= CVT_SEQ) < CVT_W)   { src = w1;  dst = (float4*)g_Wc[0]; }
    else if ((off -= CVT_W) < CVT_W)     { src = w2;  dst = (float4*)g_Wc[1]; }
    else if ((off -= CVT_W) < CVT_G) {
        ((float4*)g_G)[off] = make_float4(0.f, 0.f, 0.f, 0.f);
        return;
    }
    else return;
    float4 v = src[off];
    v.x = __uint_as_float(f2tf32(v.x));
    v.y = __uint_as_float(f2tf32(v.y));
    v.z = __uint_as_float(f2tf32(v.z));
    v.w = __uint_as_float(f2tf32(v.w));
    dst[off] = v;
}

// ---------------- ftsT[z] = W[z] x seq[z]^T ----------------
__global__ __launch_bounds__(256, 2) void k_gemm_ftsT() {
    const int z = blockIdx.z;
    const float* A = g_Wc[z & 1];
    const float* B = g_seqc[z >> 1];
    float* __restrict__ C = g_fts[z];
    const int m0 = blockIdx.y * 128, n0 = blockIdx.x * 128;

    float acc[4][4][4];
    ZERO_ACC4(acc);
    nt_core(A, N_INF, B, N_INF, m0, n0, N_INF, acc);

    const int lane = threadIdx.x & 31, warp = threadIdx.x >> 5;
    const int g = lane >> 2, t4 = lane & 3;
    const int wr = (warp & 1) * 64, wc = (warp >> 1) * 32;
#pragma unroll
    for (int mt = 0; mt < 4; mt++)
#pragma unroll
        for (int nt = 0; nt < 4; nt++) {
            int row = m0 + wr + mt * 16 + g;
            int col = n0 + wc + nt * 8 + 2 * t4;
            float2 v01, v23;
            v01.x = __uint_as_float(f2tf32(acc[mt][nt][0]));
            v01.y = __uint_as_float(f2tf32(acc[mt][nt][1]));
            v23.x = __uint_as_float(f2tf32(acc[mt][nt][2]));
            v23.y = __uint_as_float(f2tf32(acc[mt][nt][3]));
            *(float2*)(C + (size_t)row * N_NODES + col) = v01;
            *(float2*)(C + (size_t)(row + 8) * N_NODES + col) = v23;
        }
}

// ---------------- h[z] = prelu(adj x ftsT^T + b) ----------------
__global__ __launch_bounds__(256, 2) void k_gemm_prop(
    const float* __restrict__ adj, const float* __restrict__ diff,
    const float* __restrict__ b1,  const float* __restrict__ b2,
    const float* __restrict__ a1,  const float* __restrict__ a2)
{
    const int z = blockIdx.z;
    const float* A = (z & 1) ? diff : adj;
    const float* B = g_fts[z];
    const float* bias = (z & 1) ? b2 : b1;
    const float slope = (z & 1) ? a2[0] : a1[0];
    float* __restrict__ C = g_h[z];
    const int m0 = blockIdx.y * 128, n0 = blockIdx.x * 128;

    float acc[4][4][4];
    ZERO_ACC4(acc);
    nt_core(A, N_NODES, B, N_NODES, m0, n0, N_NODES, acc);

    const int lane = threadIdx.x & 31, warp = threadIdx.x >> 5;
    const int g = lane >> 2, t4 = lane & 3;
    const int wr = (warp & 1) * 64, wc = (warp >> 1) * 32;
#pragma unroll
    for (int mt = 0; mt < 4; mt++)
#pragma unroll
        for (int nt = 0; nt < 4; nt++) {
            int row = m0 + wr + mt * 16 + g;
            int col = n0 + wc + nt * 8 + 2 * t4;
            float b0 = bias[col], b1v = bias[col + 1];
            float2 v01, v23;
            v01.x = acc[mt][nt][0] + b0;  v01.y = acc[mt][nt][1] + b1v;
            v23.x = acc[mt][nt][2] + b0;  v23.y = acc[mt][nt][3] + b1v;
            v01.x = (v01.x >= 0.0f) ? v01.x : slope * v01.x;
            v01.y = (v01.y >= 0.0f) ? v01.y : slope * v01.y;
            v23.x = (v23.x >= 0.0f) ? v23.x : slope * v23.x;
            v23.y = (v23.y >= 0.0f) ? v23.y : slope * v23.y;
            *(float2*)(C + (size_t)row * N_HID + col) = v01;
            *(float2*)(C + (size_t)(row + 8) * N_HID + col) = v23;
        }
}

// ---------------- node_sq = (Zn Zn^T)^2, SYMMETRIC ----------------
__global__ __launch_bounds__(256, 2) void k_gemm_node() {
    const int bx = blockIdx.x, by = blockIdx.y;
    if (bx < by) return;
    const int m0 = by * 128, n0 = bx * 128;

    float acc[4][4][4];
    ZERO_ACC4(acc);
    nt_core(g_Z, N_HID, g_Z, N_HID, m0, n0, N_HID, acc);

    const int t = threadIdx.x;
    const int lane = t & 31, warp = t >> 5;
    const int g = lane >> 2, t4 = lane & 3;
    const int wr = (warp & 1) * 64, wc = (warp >> 1) * 32;

    extern __shared__ char smem[];
    float* smf = (float*)smem;
    const bool mirror = (bx != by);
    if (mirror) __syncthreads();

#pragma unroll
    for (int mt = 0; mt < 4; mt++) {
        int rowl = wr + mt * 16 + g;
        float ri0 = g_rninv[m0 + rowl], ri1 = g_rninv[m0 + rowl + 8];
#pragma unroll
        for (int nt = 0; nt < 4; nt++) {
            int coll = wc + nt * 8 + 2 * t4;
            float c0 = g_rninv[n0 + coll], c1 = g_rninv[n0 + coll + 1];
            float x0 = acc[mt][nt][0] * ri0 * c0;
            float x1 = acc[mt][nt][1] * ri0 * c1;
            float x2 = acc[mt][nt][2] * ri1 * c0;
            float x3 = acc[mt][nt][3] * ri1 * c1;
            float2 v01, v23;
            v01.x = x0 * x0; v01.y = x1 * x1;
            v23.x = x2 * x2; v23.y = x3 * x3;
            *(float2*)(g_node_sq + (size_t)(m0 + rowl) * N_NODES + n0 + coll) = v01;
            *(float2*)(g_node_sq + (size_t)(m0 + rowl + 8) * N_NODES + n0 + coll) = v23;
            if (mirror) {
                smf[(coll + 0) * 132 + rowl]     = v01.x;
                smf[(coll + 1) * 132 + rowl]     = v01.y;
                smf[(coll + 0) * 132 + rowl + 8] = v23.x;
                smf[(coll + 1) * 132 + rowl + 8] = v23.y;
            }
        }
    }
    if (mirror) {
        __syncthreads();
#pragma unroll
        for (int i = 0; i < 16; i++) {
            int idx4 = t + i * 256;
            int r2 = idx4 >> 5, c4 = idx4 & 31;
            float4 vv = *(float4*)(smf + r2 * 132 + c4 * 4);
            *(float4*)(g_node_sq + (size_t)(n0 + r2) * N_NODES + m0 + c4 * 4) = vv;
        }
    }
}

// ---------------- fused: Z = h1+h2 (tf32), rninv, and Z^T ----------------
__global__ __launch_bounds__(256) void k_compute_Zt() {
    __shared__ float sz[32 * 521];
    const int t = threadIdx.x;
    const int r = t >> 3, j = t & 7;
    const int R0 = blockIdx.x * 32;
    const size_t rowoff = (size_t)(R0 + r) * N_HID;

    float ss = 0.0f;
#pragma unroll
    for (int i = 0; i < 16; i++) {
        int c = j * 64 + i * 4;
        float4 a = *(const float4*)(g_h[0] + rowoff + c);
        float4 b = *(const float4*)(g_h[1] + rowoff + c);
        float4 z;
        z.x = __uint_as_float(f2tf32(a.x + b.x));
        z.y = __uint_as_float(f2tf32(a.y + b.y));
        z.z = __uint_as_float(f2tf32(a.z + b.z));
        z.w = __uint_as_float(f2tf32(a.w + b.w));
        *(float4*)(g_Z + rowoff + c) = z;
        sz[r * 521 + c + 0] = z.x;
        sz[r * 521 + c + 1] = z.y;
        sz[r * 521 + c + 2] = z.z;
        sz[r * 521 + c + 3] = z.w;
        ss += z.x * z.x + z.y * z.y + z.z * z.z + z.w * z.w;
    }
#pragma unroll
    for (int d = 4; d > 0; d >>= 1) ss += __shfl_xor_sync(0xFFFFFFFFu, ss, d);
    if (j == 0) g_rninv[R0 + r] = 1.0f / fmaxf(sqrtf(ss), 1e-12f);
    __syncthreads();

#pragma unroll
    for (int cc = 0; cc < 2; cc++) {
        int c = t * 2 + cc;
        float4 v;
        float* dst = g_Zt + (size_t)c * N_NODES + R0;
#pragma unroll
        for (int rb = 0; rb < 8; rb++) {
            v.x = sz[(rb * 4 + 0) * 521 + c];
            v.y = sz[(rb * 4 + 1) * 521 + c];
            v.z = sz[(rb * 4 + 2) * 521 + c];
            v.w = sz[(rb * 4 + 3) * 521 + c];
            *(float4*)(dst + rb * 4) = v;
        }
    }
}

// ---------------- column reductions ----------------
__global__ void k_col_reduce() {
    const int mode = blockIdx.y;
    const int tx = threadIdx.x & 31;
    const int ty = threadIdx.x >> 5;
    const int col = blockIdx.x * 32 + tx;
    const float* __restrict__ src = (mode == 0) ? g_h[0] : (mode == 1) ? g_h[1] : g_Z;
    float s = 0.0f;
    for (int r = ty; r < N_NODES; r += 8) {
        float v = src[(size_t)r * N_HID + col];
        s += (mode == 2) ? v * v : v;
    }
    __shared__ float sm[8][32];
    sm[ty][tx] = s;
    __syncthreads();
    if (ty == 0) {
        float tot = 0.0f;
#pragma unroll
        for (int k = 0; k < 8; k++) tot += sm[k][tx];
        if (mode == 2) g_cninv[col] = 1.0f / fmaxf(sqrtf(tot), 1e-12f);
        else g_csum[mode][col] = tot;
    }
}

// ---------------- u = Wd @ sigmoid(colmean) ----------------
__global__ void k_compute_u(const float* __restrict__ Wd) {
    __shared__ float c1s[512], c2s[512];
    const int h = threadIdx.x;
    c1s[h] = 1.0f / (1.0f + expf(-g_csum[0][h] * (1.0f / 4096.0f)));
    c2s[h] = 1.0f / (1.0f + expf(-g_csum[1][h] * (1.0f / 4096.0f)));
    __syncthreads();
    float u1 = 0.0f, u2 = 0.0f;
    const float4* Wrow = reinterpret_cast<const float4*>(Wd + (size_t)h * N_HID);
#pragma unroll 4
    for (int k4 = 0; k4 < 128; k4++) {
        float4 w = Wrow[k4];
        int k = k4 * 4;
        u1 += w.x * c1s[k] + w.y * c1s[k + 1] + w.z * c1s[k + 2] + w.w * c1s[k + 3];
        u2 += w.x * c2s[k] + w.y * c2s[k + 1] + w.z * c2s[k + 2] + w.w * c2s[k + 3];
    }
    g_u[0][h] = u1;
    g_u[1][h] = u2;
}

// ---------------- ret ----------------
__global__ void k_ret(const float* __restrict__ bd, float* __restrict__ out) {
    const int q = blockIdx.y;
    const int n = blockIdx.x * 8 + (threadIdx.x >> 5);
    const int lane = threadIdx.x & 31;
    const float* __restrict__ h = (q == 0) ? g_h[1] : (q == 1) ? g_h[0]
                                : (q == 2) ? g_h[3] : g_h[2];
    const float* __restrict__ u = (q == 0 || q == 2) ? g_u[0] : g_u[1];
    float s = 0.0f;
    for (int k = lane; k < N_HID; k += 32)
        s += h[(size_t)n * N_HID + k] * u[k];
#pragma unroll
    for (int o = 16; o > 0; o >>= 1) s += __shfl_down_sync(0xFFFFFFFFu, s, o);
    if (lane == 0) out[q * N_NODES + n] = s + bd[0];
}

// ---------------- G = Z^T Z via fast NT core on Zt (split-K=8) ----------------
__global__ __launch_bounds__(256, 2) void k_gemm_G() {
    const int m0 = blockIdx.y * 128, n0 = blockIdx.x * 128;
    const float* Zt = g_Zt + (size_t)blockIdx.z * 512;

    float acc[4][4][4];
    ZERO_ACC4(acc);
    nt_core(Zt, N_NODES, Zt, N_NODES, m0, n0, 512, acc);

    const int lane = threadIdx.x & 31, warp = threadIdx.x >> 5;
    const int g = lane >> 2, t4 = lane & 3;
    const int wr = (warp & 1) * 64, wc = (warp >> 1) * 32;
#pragma unroll
    for (int mt = 0; mt < 4; mt++)
#pragma unroll
        for (int nt = 0; nt < 4; nt++)
#pragma unroll
            for (int e = 0; e < 4; e++) {
                int row = m0 + wr + mt * 16 + g + (e >> 1) * 8;
                int col = n0 + wc + nt * 8 + 2 * t4 + (e & 1);
                atomicAdd(&g_G[(size_t)row * N_HID + col], acc[mt][nt][e]);
            }
}

// ---------------- feat loss: 64-thread register bitonic over 512 ----------------
__global__ __launch_bounds__(64) void k_feat_loss(const int* __restrict__ feat_index) {
    const int h = blockIdx.x;
    const int t = threadIdx.x;
    __shared__ float sm[512];
    __shared__ float s_diag;

    const float ch = g_cninv[h];
    float v[8];
    {
        const float4* Gr = reinterpret_cast<const float4*>(g_G + (size_t)h * N_HID) + t * 2;
        float4 a = Gr[0], b = Gr[1];
        int base = t * 8;
        float f;
        f = a.x * ch * g_cninv[base + 0]; v[0] = f * f;
        f = a.y * ch * g_cninv[base + 1]; v[1] = f * f;
        f = a.z * ch * g_cninv[base + 2]; v[2] = f * f;
        f = a.w * ch * g_cninv[base + 3]; v[3] = f * f;
        f = b.x * ch * g_cninv[base + 4]; v[4] = f * f;
        f = b.y * ch * g_cninv[base + 5]; v[5] = f * f;
        f = b.z * ch * g_cninv[base + 6]; v[6] = f * f;
        f = b.w * ch * g_cninv[base + 7]; v[7] = f * f;
    }
    if (t == (h >> 3)) s_diag = v[h & 7];
    __syncthreads();
    const float diag = s_diag;

    for (int kk = 2; kk <= 512; kk <<= 1) {
        for (int j = kk >> 1; j > 0; j >>= 1) {
            if (j >= 256) {
                const int d = j >> 3;
                const bool lower = (t & d) == 0;
                const bool up = ((t & (kk >> 3)) == 0);
                const bool keepmin = (up == lower);
                __syncthreads();
#pragma unroll
                for (int e = 0; e < 8; e++) sm[t * 8 + e] = v[e];
                __syncthreads();
#pragma unroll
                for (int e = 0; e < 8; e++) {
                    float o = sm[(t ^ d) * 8 + e];
                    v[e] = keepmin ? fminf(v[e], o) : fmaxf(v[e], o);
                }
            } else if (j >= 8) {
                const int d = j >> 3;
                const bool lower = (t & d) == 0;
                const bool up = ((t & (kk >> 3)) == 0);
                const bool keepmin = (up == lower);
#pragma unroll
                for (int e = 0; e < 8; e++) {
                    float o = __shfl_xor_sync(0xFFFFFFFFu, v[e], d);
                    v[e] = keepmin ? fminf(v[e], o) : fmaxf(v[e], o);
                }
            } else {
#pragma unroll
                for (int e = 0; e < 8; e++) {
                    if ((e & j) == 0) {
                        int p = e | j;
                        bool up = ((((t << 3) | e) & kk) == 0);
                        float a = v[e], b = v[p];
                        float lo = fminf(a, b), hi = fmaxf(a, b);
                        v[e] = up ? lo : hi;
                        v[p] = up ? hi : lo;
                    }
                }
            }
        }
    }
    __syncthreads();
#pragma unroll
    for (int e = 0; e < 8; e++) sm[t * 8 + e] = v[e];
    __syncthreads();
    if (t == 0) {
        float neg = 0.0f;
#pragma unroll
        for (int s = 0; s < N_S; s++) neg += expf(2.0f * sm[feat_index[s]]);
        float pos = expf(2.0f * diag);
        atomicAdd(&g_feat_loss, (logf(neg) - logf(pos)) * (1.0f / 512.0f));
    }
}

// ---------------- node loss: register/shuffle bitonic ----------------
__global__ __launch_bounds__(512) void k_node_sel(const float* __restrict__ adj_label,
                                                  const int* __restrict__ node_index) {
    const int i = blockIdx.x;
    const int t = threadIdx.x;
    __shared__ float sm[4096];
    __shared__ float red[16];
    const float* __restrict__ trow = g_node_sq + (size_t)i * N_NODES;
    const float* __restrict__ lrow = adj_label + (size_t)i * N_NODES;

    float v[8];
    float pos = 0.0f;
    {
        const float4* t4p = reinterpret_cast<const float4*>(trow) + t * 2;
        const float4* l4p = reinterpret_cast<const float4*>(lrow) + t * 2;
        float4 a = t4p[0], b = t4p[1];
        float4 la = l4p[0], lb = l4p[1];
        v[0] = a.x; v[1] = a.y; v[2] = a.z; v[3] = a.w;
        v[4] = b.x; v[5] = b.y; v[6] = b.z; v[7] = b.w;
        pos += __expf(2.0f * a.x) * la.x + __expf(2.0f * a.y) * la.y
             + __expf(2.0f * a.z) * la.z + __expf(2.0f * a.w) * la.w
             + __expf(2.0f * b.x) * lb.x + __expf(2.0f * b.y) * lb.y
             + __expf(2.0f * b.z) * lb.z + __expf(2.0f * b.w) * lb.w;
    }
#pragma unroll
    for (int o = 16; o > 0; o >>= 1) pos += __shfl_xor_sync(0xFFFFFFFFu, pos, o);
    if ((t & 31) == 0) red[t >> 5] = pos;
    __syncthreads();
    float posSum = 0.0f;
#pragma unroll
    for (int w = 0; w < 16; w++) posSum += red[w];

    for (int kk = 2; kk <= 4096; kk <<= 1) {
        for (int j = kk >> 1; j > 0; j >>= 1) {
            if (j >= 256) {
                const int d = j >> 3;
                const bool lower = (t & d) == 0;
                const bool up = ((t & (kk >> 3)) == 0);
                const bool keepmin = (up == lower);
                __syncthreads();
#pragma unroll
                for (int e = 0; e < 8; e++) sm[t * 8 + e] = v[e];
                __syncthreads();
#pragma unroll
                for (int e = 0; e < 8; e++) {
                    float o = sm[(t ^ d) * 8 + e];
                    v[e] = keepmin ? fminf(v[e], o) : fmaxf(v[e], o);
                }
            } else if (j >= 8) {
                const int d = j >> 3;
                const bool lower = (t & d) == 0;
                const bool up = ((t & (kk >> 3)) == 0);
                const bool keepmin = (up == lower);
#pragma unroll
                for (int e = 0; e < 8; e++) {
                    float o = __shfl_xor_sync(0xFFFFFFFFu, v[e], d);
                    v[e] = keepmin ? fminf(v[e], o) : fmaxf(v[e], o);
                }
            } else {
#pragma unroll
                for (int e = 0; e < 8; e++) {
                    if ((e & j) == 0) {
                        int p = e | j;
                        bool up = ((((t << 3) | e) & kk) == 0);
                        float a = v[e], b = v[p];
                        float lo = fminf(a, b), hi = fmaxf(a, b);
                        v[e] = up ? lo : hi;
                        v[p] = up ? hi : lo;
                    }
                }
            }
        }
    }
    __syncthreads();
#pragma unroll
    for (int e = 0; e < 8; e++) sm[t * 8 + e] = v[e];
    __syncthreads();
    if (t == 0) {
        float neg = 0.0f;
#pragma unroll
        for (int s = 0; s < N_S; s++) neg += __expf(2.0f * sm[node_index[s]]);
        atomicAdd(&g_node_loss, (logf(neg) - logf(posSum)) * (1.0f / 4096.0f));
    }
}

// ---------------- finalize ----------------
__global__ void k_finalize(float* __restrict__ out) {
    out[4 * N_NODES + 0] = g_feat_loss;
    out[4 * N_NODES + 1] = g_node_loss;
}

// ---------------- launch ----------------
extern "C" void kernel_launch(void* const* d_in, const int* in_sizes, int n_in,
                              void* d_out, int out_size) {
    const float* seq1      = (const float*)d_in[0];
    const float* seq2      = (const float*)d_in[1];
    const float* adj       = (const float*)d_in[2];
    const float* diff      = (const float*)d_in[3];
    const float* adj_label = (const float*)d_in[4];
    const int*   feat_idx  = (const int*)d_in[5];
    const int*   node_idx  = (const int*)d_in[6];
    const float* b1        = (const float*)d_in[8];
    const float* a1        = (const float*)d_in[9];
    const float* b2        = (const float*)d_in[11];
    const float* a2        = (const float*)d_in[12];
    const float* Wd        = (const float*)d_in[13];
    const float* bd        = (const float*)d_in[14];
    float* out = (float*)d_out;

    static cudaStream_t s1 = nullptr;
    static cudaEvent_t evFork = nullptr, evNode = nullptr;
    if (!s1) {
        cudaStreamCreateWithFlags(&s1, cudaStreamNonBlocking);
        cudaEventCreateWithFlags(&evFork, cudaEventDisableTiming);
        cudaEventCreateWithFlags(&evNode, cudaEventDisableTiming);
        cudaFuncSetAttribute(k_gemm_ftsT, cudaFuncAttributeMaxDynamicSharedMemorySize, SMEM_TOTAL_G);
        cudaFuncSetAttribute(k_gemm_prop, cudaFuncAttributeMaxDynamicSharedMemorySize, SMEM_TOTAL_G);
        cudaFuncSetAttribute(k_gemm_node, cudaFuncAttributeMaxDynamicSharedMemorySize, SMEM_TOTAL_G);
        cudaFuncSetAttribute(k_gemm_G,    cudaFuncAttributeMaxDynamicSharedMemorySize, SMEM_TOTAL_G);
    }

    // ---- main chain (stream 0) ----
    k_cvt_all<<<(CVT_TOT + 255) / 256, 256>>>(
        (const float4*)seq1, (const float4*)seq2,
        (const float4*)d_in[7], (const float4*)d_in[10]);
    k_gemm_ftsT<<<dim3(32, 4, 4), 256, SMEM_TOTAL_G>>>();
    k_gemm_prop<<<dim3(4, 32, 4), 256, SMEM_TOTAL_G>>>(adj, diff, b1, b2, a1, a2);
    k_compute_Zt<<<128, 256>>>();

    // ---- fork: node path on s1 (depends only on Z, rninv) ----
    cudaEventRecord(evFork, 0);
    cudaStreamWaitEvent(s1, evFork, 0);
    k_gemm_node<<<dim3(32, 32), 256, SMEM_TOTAL_G, s1>>>();
    k_node_sel<<<N_NODES, 512, 0, s1>>>(adj_label, node_idx);
    cudaEventRecord(evNode, s1);

    // ---- feat/ret path stays on stream 0 ----
    k_col_reduce<<<dim3(16, 3), 256>>>();
    k_compute_u<<<1, 512>>>(Wd);
    k_ret<<<dim3(512, 4), 256>>>(bd, out);
    k_gemm_G<<<dim3(4, 4, 8), 256, SMEM_TOTAL_G>>>();
    k_feat_loss<<<512, 64>>>(feat_idx);

    // ---- join ----
    cudaStreamWaitEvent(0, evNode, 0);
    k_finalize<<<1, 1>>>(out);
}

// round 16
// speedup vs baseline: 1.0681x; 1.0178x over previous
#include <cuda_runtime.h>
#include <math.h>
#include <stdint.h>

#define N_NODES 4096
#define N_HID   512
#define N_INF   512
#define N_S     10

// ---------------- scratch ----------------
__device__ float g_seqc[2][N_NODES * N_INF];
__device__ float g_Wc[2][N_HID * N_INF];
__device__ float g_fts[4][N_HID * N_NODES];
__device__ float g_h[4][N_NODES * N_HID];
__device__ float g_Z[N_NODES * N_HID];
__device__ float g_Zt[N_HID * N_NODES];
__device__ float g_G[N_HID * N_HID];
__device__ float g_node_sq[(size_t)N_NODES * N_NODES];
__device__ float g_csum[2][N_HID];
__device__ float g_u[2][N_HID];
__device__ float g_rninv[N_NODES];
__device__ float g_cninv[N_HID];
__device__ float g_feat_loss;
__device__ float g_node_loss;

// ---------------- helpers ----------------
__device__ __forceinline__ unsigned f2tf32(float x) {
    unsigned r;
    asm("cvt.rna.tf32.f32 %0, %1;" : "=r"(r) : "f"(x));
    return r;
}

__device__ __forceinline__ void mma8(float (&c)[4], const unsigned (&a)[4],
                                     const unsigned (&b)[2]) {
    asm volatile(
        "mma.sync.aligned.m16n8k8.row.col.f32.tf32.tf32.f32 "
        "{%0,%1,%2,%3}, {%4,%5,%6,%7}, {%8,%9}, {%0,%1,%2,%3};\n"
        : "+f"(c[0]), "+f"(c[1]), "+f"(c[2]), "+f"(c[3])
        : "r"(a[0]), "r"(a[1]), "r"(a[2]), "r"(a[3]), "r"(b[0]), "r"(b[1]));
}

__device__ __forceinline__ void ldsm_x4(unsigned (&r)[4], uint32_t addr) {
    asm volatile("ldmatrix.sync.aligned.m8n8.x4.shared.b16 {%0,%1,%2,%3}, [%4];"
                 : "=r"(r[0]), "=r"(r[1]), "=r"(r[2]), "=r"(r[3]) : "r"(addr));
}

__device__ __forceinline__ void cpa16(uint32_t smem, const void* gmem) {
    asm volatile("cp.async.cg.shared.global [%0], [%1], 16;" :: "r"(smem), "l"(gmem));
}

// =========================================================================
// NT pipelined core (R8 config): C[128,128], 2 CTAs/SM, BK=32, 3 stages.
// =========================================================================
#define STG_BYTES 32768
#define STG_BOFF  16384
#define SMEM_TOTAL_G (3 * STG_BYTES)

__device__ __forceinline__ void nt_core(
    const float* __restrict__ A, int lda,
    const float* __restrict__ B, int ldb,
    int m0, int n0, int K, float (&acc)[4][4][4])
{
    extern __shared__ char smem[];
    const uint32_t sbase = (uint32_t)__cvta_generic_to_shared(smem);

    const int t = threadIdx.x;
    const int lane = t & 31, warp = t >> 5;
    const int wr = (warp & 1) * 64, wc = (warp >> 1) * 32;
    const int q = lane >> 3, rowin = lane & 7;
    const int qlo = q & 1, qhi = q >> 1;

    uint32_t aR[4], aSw[4], bR[2], bSw[2];
#pragma unroll
    for (int mt = 0; mt < 4; mt++) {
        int r = wr + mt * 16 + qlo * 8 + rowin;
        aR[mt] = r * 128; aSw[mt] = r & 7;
    }
#pragma unroll
    for (int np = 0; np < 2; np++) {
        int r = wc + (np * 2 + qhi) * 8 + rowin;
        bR[np] = r * 128; bSw[np] = r & 7;
    }

    const int KT = K >> 5;

    auto issue = [&](int kt, int buf) {
        const uint32_t sa = sbase + buf * STG_BYTES;
        const uint32_t sb = sa + STG_BOFF;
#pragma unroll
        for (int j = 0; j < 4; j++) {
            int c = t + j * 256;
            int r = c >> 3, c16 = c & 7;
            uint32_t sw = ((unsigned)(c16 ^ (r & 7))) << 4;
            cpa16(sa + r * 128 + sw, A + (size_t)(m0 + r) * lda + kt * 32 + c16 * 4);
            cpa16(sb + r * 128 + sw, B + (size_t)(n0 + r) * ldb + kt * 32 + c16 * 4);
        }
        asm volatile("cp.async.commit_group;");
    };

    issue(0, 0);
    issue(1, 1);

    for (int kt = 0; kt < KT; kt++) {
        if (kt + 1 < KT) { asm volatile("cp.async.wait_group 1;"); }
        else             { asm volatile("cp.async.wait_group 0;"); }
        __syncthreads();

        const uint32_t sa = sbase + (kt % 3) * STG_BYTES;
        const uint32_t sb = sa + STG_BOFF;
#pragma unroll
        for (int ks = 0; ks < 4; ks++) {
            unsigned af[4][4], bf[4][2];
#pragma unroll
            for (int mt = 0; mt < 4; mt++) {
                uint32_t c = ks * 2 + qhi;
                ldsm_x4(af[mt], sa + aR[mt] + ((c ^ aSw[mt]) << 4));
            }
#pragma unroll
            for (int np = 0; np < 2; np++) {
                unsigned r4[4];
                uint32_t c = ks * 2 + qlo;
                ldsm_x4(r4, sb + bR[np] + ((c ^ bSw[np]) << 4));
                bf[np * 2 + 0][0] = r4[0]; bf[np * 2 + 0][1] = r4[1];
                bf[np * 2 + 1][0] = r4[2]; bf[np * 2 + 1][1] = r4[3];
            }
#pragma unroll
            for (int mt = 0; mt < 4; mt++)
#pragma unroll
                for (int nt = 0; nt < 4; nt++)
                    mma8(acc[mt][nt], af[mt], bf[nt]);
        }
        if (kt + 2 < KT) issue(kt + 2, (kt + 2) % 3);
    }
}

#define ZERO_ACC4(acc)                             \
    _Pragma("unroll")                              \
    for (int mt = 0; mt < 4; mt++)                 \
        _Pragma("unroll")                          \
        for (int nt = 0; nt < 4; nt++)             \
            _Pragma("unroll")                      \
            for (int e = 0; e < 4; e++) acc[mt][nt][e] = 0.0f;

// ---------------- tf32 pre-convert + zero G + zero losses ----------------
#define CVT_SEQ  524288
#define CVT_W    65536
#define CVT_G    65536
#define CVT_TOT  (2 * CVT_SEQ + 2 * CVT_W + CVT_G)

__global__ void k_cvt_all(const float4* __restrict__ s1,  const float4* __restrict__ s2,
                          const float4* __restrict__ w1,  const float4* __restrict__ w2)
{
    long off = (long)blockIdx.x * 256 + threadIdx.x;
    if (off == 0) { g_feat_loss = 0.0f; g_node_loss = 0.0f; }
    const float4* src; float4* dst;
    if (off < CVT_SEQ)                   { src = s1;  dst = (float4*)g_seqc[0]; }
    else if ((off -= CVT_SEQ) < CVT_SEQ) { src = s2;  dst = (float4*)g_seqc[1]; }
    else if ((off -= CVT_SEQ) < CVT_W)   { src = w1;  dst = (float4*)g_Wc[0]; }
    else if ((off -= CVT_W) < CVT_W)     { src = w2;  dst = (float4*)g_Wc[1]; }
    else if ((off -= CVT_W) < CVT_G) {
        ((float4*)g_G)[off] = make_float4(0.f, 0.f, 0.f, 0.f);
        return;
    }
    else return;
    float4 v = src[off];
    v.x = __uint_as_float(f2tf32(v.x));
    v.y = __uint_as_float(f2tf32(v.y));
    v.z = __uint_as_float(f2tf32(v.z));
    v.w = __uint_as_float(f2tf32(v.w));
    dst[off] = v;
}

// ---------------- ftsT[z] = W[z] x seq[z]^T ----------------
__global__ __launch_bounds__(256, 2) void k_gemm_ftsT() {
    const int z = blockIdx.z;
    const float* A = g_Wc[z & 1];
    const float* B = g_seqc[z >> 1];
    float* __restrict__ C = g_fts[z];
    const int m0 = blockIdx.y * 128, n0 = blockIdx.x * 128;

    float acc[4][4][4];
    ZERO_ACC4(acc);
    nt_core(A, N_INF, B, N_INF, m0, n0, N_INF, acc);

    const int lane = threadIdx.x & 31, warp = threadIdx.x >> 5;
    const int g = lane >> 2, t4 = lane & 3;
    const int wr = (warp & 1) * 64, wc = (warp >> 1) * 32;
#pragma unroll
    for (int mt = 0; mt < 4; mt++)
#pragma unroll
        for (int nt = 0; nt < 4; nt++) {
            int row = m0 + wr + mt * 16 + g;
            int col = n0 + wc + nt * 8 + 2 * t4;
            float2 v01, v23;
            v01.x = __uint_as_float(f2tf32(acc[mt][nt][0]));
            v01.y = __uint_as_float(f2tf32(acc[mt][nt][1]));
            v23.x = __uint_as_float(f2tf32(acc[mt][nt][2]));
            v23.y = __uint_as_float(f2tf32(acc[mt][nt][3]));
            *(float2*)(C + (size_t)row * N_NODES + col) = v01;
            *(float2*)(C + (size_t)(row + 8) * N_NODES + col) = v23;
        }
}

// ---------------- h[z] = prelu(adj x ftsT^T + b), z = zbase + blockIdx.z ----------
__global__ __launch_bounds__(256, 2) void k_gemm_prop(
    const float* __restrict__ adj, const float* __restrict__ diff,
    const float* __restrict__ b1,  const float* __restrict__ b2,
    const float* __restrict__ a1,  const float* __restrict__ a2, int zbase)
{
    const int z = zbase + blockIdx.z;
    const float* A = (z & 1) ? diff : adj;
    const float* B = g_fts[z];
    const float* bias = (z & 1) ? b2 : b1;
    const float slope = (z & 1) ? a2[0] : a1[0];
    float* __restrict__ C = g_h[z];
    const int m0 = blockIdx.y * 128, n0 = blockIdx.x * 128;

    float acc[4][4][4];
    ZERO_ACC4(acc);
    nt_core(A, N_NODES, B, N_NODES, m0, n0, N_NODES, acc);

    const int lane = threadIdx.x & 31, warp = threadIdx.x >> 5;
    const int g = lane >> 2, t4 = lane & 3;
    const int wr = (warp & 1) * 64, wc = (warp >> 1) * 32;
#pragma unroll
    for (int mt = 0; mt < 4; mt++)
#pragma unroll
        for (int nt = 0; nt < 4; nt++) {
            int row = m0 + wr + mt * 16 + g;
            int col = n0 + wc + nt * 8 + 2 * t4;
            float b0 = bias[col], b1v = bias[col + 1];
            float2 v01, v23;
            v01.x = acc[mt][nt][0] + b0;  v01.y = acc[mt][nt][1] + b1v;
            v23.x = acc[mt][nt][2] + b0;  v23.y = acc[mt][nt][3] + b1v;
            v01.x = (v01.x >= 0.0f) ? v01.x : slope * v01.x;
            v01.y = (v01.y >= 0.0f) ? v01.y : slope * v01.y;
            v23.x = (v23.x >= 0.0f) ? v23.x : slope * v23.x;
            v23.y = (v23.y >= 0.0f) ? v23.y : slope * v23.y;
            *(float2*)(C + (size_t)row * N_HID + col) = v01;
            *(float2*)(C + (size_t)(row + 8) * N_HID + col) = v23;
        }
}

// ---------------- node_sq = (Zn Zn^T)^2, SYMMETRIC ----------------
__global__ __launch_bounds__(256, 2) void k_gemm_node() {
    const int bx = blockIdx.x, by = blockIdx.y;
    if (bx < by) return;
    const int m0 = by * 128, n0 = bx * 128;

    float acc[4][4][4];
    ZERO_ACC4(acc);
    nt_core(g_Z, N_HID, g_Z, N_HID, m0, n0, N_HID, acc);

    const int t = threadIdx.x;
    const int lane = t & 31, warp = t >> 5;
    const int g = lane >> 2, t4 = lane & 3;
    const int wr = (warp & 1) * 64, wc = (warp >> 1) * 32;

    extern __shared__ char smem[];
    float* smf = (float*)smem;
    const bool mirror = (bx != by);
    if (mirror) __syncthreads();

#pragma unroll
    for (int mt = 0; mt < 4; mt++) {
        int rowl = wr + mt * 16 + g;
        float ri0 = g_rninv[m0 + rowl], ri1 = g_rninv[m0 + rowl + 8];
#pragma unroll
        for (int nt = 0; nt < 4; nt++) {
            int coll = wc + nt * 8 + 2 * t4;
            float c0 = g_rninv[n0 + coll], c1 = g_rninv[n0 + coll + 1];
            float x0 = acc[mt][nt][0] * ri0 * c0;
            float x1 = acc[mt][nt][1] * ri0 * c1;
            float x2 = acc[mt][nt][2] * ri1 * c0;
            float x3 = acc[mt][nt][3] * ri1 * c1;
            float2 v01, v23;
            v01.x = x0 * x0; v01.y = x1 * x1;
            v23.x = x2 * x2; v23.y = x3 * x3;
            *(float2*)(g_node_sq + (size_t)(m0 + rowl) * N_NODES + n0 + coll) = v01;
            *(float2*)(g_node_sq + (size_t)(m0 + rowl + 8) * N_NODES + n0 + coll) = v23;
            if (mirror) {
                smf[(coll + 0) * 132 + rowl]     = v01.x;
                smf[(coll + 1) * 132 + rowl]     = v01.y;
                smf[(coll + 0) * 132 + rowl + 8] = v23.x;
                smf[(coll + 1) * 132 + rowl + 8] = v23.y;
            }
        }
    }
    if (mirror) {
        __syncthreads();
#pragma unroll
        for (int i = 0; i < 16; i++) {
            int idx4 = t + i * 256;
            int r2 = idx4 >> 5, c4 = idx4 & 31;
            float4 vv = *(float4*)(smf + r2 * 132 + c4 * 4);
            *(float4*)(g_node_sq + (size_t)(n0 + r2) * N_NODES + m0 + c4 * 4) = vv;
        }
    }
}

// ---------------- fused: Z = h1+h2 (tf32), rninv, and Z^T ----------------
__global__ __launch_bounds__(256) void k_compute_Zt() {
    __shared__ float sz[32 * 521];
    const int t = threadIdx.x;
    const int r = t >> 3, j = t & 7;
    const int R0 = blockIdx.x * 32;
    const size_t rowoff = (size_t)(R0 + r) * N_HID;

    float ss = 0.0f;
#pragma unroll
    for (int i = 0; i < 16; i++) {
        int c = j * 64 + i * 4;
        float4 a = *(const float4*)(g_h[0] + rowoff + c);
        float4 b = *(const float4*)(g_h[1] + rowoff + c);
        float4 z;
        z.x = __uint_as_float(f2tf32(a.x + b.x));
        z.y = __uint_as_float(f2tf32(a.y + b.y));
        z.z = __uint_as_float(f2tf32(a.z + b.z));
        z.w = __uint_as_float(f2tf32(a.w + b.w));
        *(float4*)(g_Z + rowoff + c) = z;
        sz[r * 521 + c + 0] = z.x;
        sz[r * 521 + c + 1] = z.y;
        sz[r * 521 + c + 2] = z.z;
        sz[r * 521 + c + 3] = z.w;
        ss += z.x * z.x + z.y * z.y + z.z * z.z + z.w * z.w;
    }
#pragma unroll
    for (int d = 4; d > 0; d >>= 1) ss += __shfl_xor_sync(0xFFFFFFFFu, ss, d);
    if (j == 0) g_rninv[R0 + r] = 1.0f / fmaxf(sqrtf(ss), 1e-12f);
    __syncthreads();

#pragma unroll
    for (int cc = 0; cc < 2; cc++) {
        int c = t * 2 + cc;
        float4 v;
        float* dst = g_Zt + (size_t)c * N_NODES + R0;
#pragma unroll
        for (int rb = 0; rb < 8; rb++) {
            v.x = sz[(rb * 4 + 0) * 521 + c];
            v.y = sz[(rb * 4 + 1) * 521 + c];
            v.z = sz[(rb * 4 + 2) * 521 + c];
            v.w = sz[(rb * 4 + 3) * 521 + c];
            *(float4*)(dst + rb * 4) = v;
        }
    }
}

// ---------------- column reductions ----------------
__global__ void k_col_reduce() {
    const int mode = blockIdx.y;
    const int tx = threadIdx.x & 31;
    const int ty = threadIdx.x >> 5;
    const int col = blockIdx.x * 32 + tx;
    const float* __restrict__ src = (mode == 0) ? g_h[0] : (mode == 1) ? g_h[1] : g_Z;
    float s = 0.0f;
    for (int r = ty; r < N_NODES; r += 8) {
        float v = src[(size_t)r * N_HID + col];
        s += (mode == 2) ? v * v : v;
    }
    __shared__ float sm[8][32];
    sm[ty][tx] = s;
    __syncthreads();
    if (ty == 0) {
        float tot = 0.0f;
#pragma unroll
        for (int k = 0; k < 8; k++) tot += sm[k][tx];
        if (mode == 2) g_cninv[col] = 1.0f / fmaxf(sqrtf(tot), 1e-12f);
        else g_csum[mode][col] = tot;
    }
}

// ---------------- u = Wd @ sigmoid(colmean) ----------------
__global__ void k_compute_u(const float* __restrict__ Wd) {
    __shared__ float c1s[512], c2s[512];
    const int h = threadIdx.x;
    c1s[h] = 1.0f / (1.0f + expf(-g_csum[0][h] * (1.0f / 4096.0f)));
    c2s[h] = 1.0f / (1.0f + expf(-g_csum[1][h] * (1.0f / 4096.0f)));
    __syncthreads();
    float u1 = 0.0f, u2 = 0.0f;
    const float4* Wrow = reinterpret_cast<const float4*>(Wd + (size_t)h * N_HID);
#pragma unroll 4
    for (int k4 = 0; k4 < 128; k4++) {
        float4 w = Wrow[k4];
        int k = k4 * 4;
        u1 += w.x * c1s[k] + w.y * c1s[k + 1] + w.z * c1s[k + 2] + w.w * c1s[k + 3];
        u2 += w.x * c2s[k] + w.y * c2s[k + 1] + w.z * c2s[k + 2] + w.w * c2s[k + 3];
    }
    g_u[0][h] = u1;
    g_u[1][h] = u2;
}

// ---------------- ret ----------------
__global__ void k_ret(const float* __restrict__ bd, float* __restrict__ out) {
    const int q = blockIdx.y;
    const int n = blockIdx.x * 8 + (threadIdx.x >> 5);
    const int lane = threadIdx.x & 31;
    const float* __restrict__ h = (q == 0) ? g_h[1] : (q == 1) ? g_h[0]
                                : (q == 2) ? g_h[3] : g_h[2];
    const float* __restrict__ u = (q == 0 || q == 2) ? g_u[0] : g_u[1];
    float s = 0.0f;
    for (int k = lane; k < N_HID; k += 32)
        s += h[(size_t)n * N_HID + k] * u[k];
#pragma unroll
    for (int o = 16; o > 0; o >>= 1) s += __shfl_down_sync(0xFFFFFFFFu, s, o);
    if (lane == 0) out[q * N_NODES + n] = s + bd[0];
}

// ---------------- G = Z^T Z via fast NT core on Zt (split-K=8) ----------------
__global__ __launch_bounds__(256, 2) void k_gemm_G() {
    const int m0 = blockIdx.y * 128, n0 = blockIdx.x * 128;
    const float* Zt = g_Zt + (size_t)blockIdx.z * 512;

    float acc[4][4][4];
    ZERO_ACC4(acc);
    nt_core(Zt, N_NODES, Zt, N_NODES, m0, n0, 512, acc);

    const int lane = threadIdx.x & 31, warp = threadIdx.x >> 5;
    const int g = lane >> 2, t4 = lane & 3;
    const int wr = (warp & 1) * 64, wc = (warp >> 1) * 32;
#pragma unroll
    for (int mt = 0; mt < 4; mt++)
#pragma unroll
        for (int nt = 0; nt < 4; nt++)
#pragma unroll
            for (int e = 0; e < 4; e++) {
                int row = m0 + wr + mt * 16 + g + (e >> 1) * 8;
                int col = n0 + wc + nt * 8 + 2 * t4 + (e & 1);
                atomicAdd(&g_G[(size_t)row * N_HID + col], acc[mt][nt][e]);
            }
}

// ---------------- feat loss: 64-thread register bitonic over 512 ----------------
__global__ __launch_bounds__(64) void k_feat_loss(const int* __restrict__ feat_index) {
    const int h = blockIdx.x;
    const int t = threadIdx.x;
    __shared__ float sm[512];
    __shared__ float s_diag;

    const float ch = g_cninv[h];
    float v[8];
    {
        const float4* Gr = reinterpret_cast<const float4*>(g_G + (size_t)h * N_HID) + t * 2;
        float4 a = Gr[0], b = Gr[1];
        int base = t * 8;
        float f;
        f = a.x * ch * g_cninv[base + 0]; v[0] = f * f;
        f = a.y * ch * g_cninv[base + 1]; v[1] = f * f;
        f = a.z * ch * g_cninv[base + 2]; v[2] = f * f;
        f = a.w * ch * g_cninv[base + 3]; v[3] = f * f;
        f = b.x * ch * g_cninv[base + 4]; v[4] = f * f;
        f = b.y * ch * g_cninv[base + 5]; v[5] = f * f;
        f = b.z * ch * g_cninv[base + 6]; v[6] = f * f;
        f = b.w * ch * g_cninv[base + 7]; v[7] = f * f;
    }
    if (t == (h >> 3)) s_diag = v[h & 7];
    __syncthreads();
    const float diag = s_diag;

    for (int kk = 2; kk <= 512; kk <<= 1) {
        for (int j = kk >> 1; j > 0; j >>= 1) {
            if (j >= 256) {
                const int d = j >> 3;
                const bool lower = (t & d) == 0;
                const bool up = ((t & (kk >> 3)) == 0);
                const bool keepmin = (up == lower);
                __syncthreads();
#pragma unroll
                for (int e = 0; e < 8; e++) sm[t * 8 + e] = v[e];
                __syncthreads();
#pragma unroll
                for (int e = 0; e < 8; e++) {
                    float o = sm[(t ^ d) * 8 + e];
                    v[e] = keepmin ? fminf(v[e], o) : fmaxf(v[e], o);
                }
            } else if (j >= 8) {
                const int d = j >> 3;
                const bool lower = (t & d) == 0;
                const bool up = ((t & (kk >> 3)) == 0);
                const bool keepmin = (up == lower);
#pragma unroll
                for (int e = 0; e < 8; e++) {
                    float o = __shfl_xor_sync(0xFFFFFFFFu, v[e], d);
                    v[e] = keepmin ? fminf(v[e], o) : fmaxf(v[e], o);
                }
            } else {
#pragma unroll
                for (int e = 0; e < 8; e++) {
                    if ((e & j) == 0) {
                        int p = e | j;
                        bool up = ((((t << 3) | e) & kk) == 0);
                        float a = v[e], b = v[p];
                        float lo = fminf(a, b), hi = fmaxf(a, b);
                        v[e] = up ? lo : hi;
                        v[p] = up ? hi : lo;
                    }
                }
            }
        }
    }
    __syncthreads();
#pragma unroll
    for (int e = 0; e < 8; e++) sm[t * 8 + e] = v[e];
    __syncthreads();
    if (t == 0) {
        float neg = 0.0f;
#pragma unroll
        for (int s = 0; s < N_S; s++) neg += expf(2.0f * sm[feat_index[s]]);
        float pos = expf(2.0f * diag);
        atomicAdd(&g_feat_loss, (logf(neg) - logf(pos)) * (1.0f / 512.0f));
    }
}

// ---------------- node loss: register/shuffle bitonic ----------------
__global__ __launch_bounds__(512) void k_node_sel(const float* __restrict__ adj_label,
                                                  const int* __restrict__ node_index) {
    const int i = blockIdx.x;
    const int t = threadIdx.x;
    __shared__ float sm[4096];
    __shared__ float red[16];
    const float* __restrict__ trow = g_node_sq + (size_t)i * N_NODES;
    const float* __restrict__ lrow = adj_label + (size_t)i * N_NODES;

    float v[8];
    float pos = 0.0f;
    {
        const float4* t4p = reinterpret_cast<const float4*>(trow) + t * 2;
        const float4* l4p = reinterpret_cast<const float4*>(lrow) + t * 2;
        float4 a = t4p[0], b = t4p[1];
        float4 la = l4p[0], lb = l4p[1];
        v[0] = a.x; v[1] = a.y; v[2] = a.z; v[3] = a.w;
        v[4] = b.x; v[5] = b.y; v[6] = b.z; v[7] = b.w;
        pos += __expf(2.0f * a.x) * la.x + __expf(2.0f * a.y) * la.y
             + __expf(2.0f * a.z) * la.z + __expf(2.0f * a.w) * la.w
             + __expf(2.0f * b.x) * lb.x + __expf(2.0f * b.y) * lb.y
             + __expf(2.0f * b.z) * lb.z + __expf(2.0f * b.w) * lb.w;
    }
#pragma unroll
    for (int o = 16; o > 0; o >>= 1) pos += __shfl_xor_sync(0xFFFFFFFFu, pos, o);
    if ((t & 31) == 0) red[t >> 5] = pos;
    __syncthreads();
    float posSum = 0.0f;
#pragma unroll
    for (int w = 0; w < 16; w++) posSum += red[w];

    for (int kk = 2; kk <= 4096; kk <<= 1) {
        for (int j = kk >> 1; j > 0; j >>= 1) {
            if (j >= 256) {
                const int d = j >> 3;
                const bool lower = (t & d) == 0;
                const bool up = ((t & (kk >> 3)) == 0);
                const bool keepmin = (up == lower);
                __syncthreads();
#pragma unroll
                for (int e = 0; e < 8; e++) sm[t * 8 + e] = v[e];
                __syncthreads();
#pragma unroll
                for (int e = 0; e < 8; e++) {
                    float o = sm[(t ^ d) * 8 + e];
                    v[e] = keepmin ? fminf(v[e], o) : fmaxf(v[e], o);
                }
            } else if (j >= 8) {
                const int d = j >> 3;
                const bool lower = (t & d) == 0;
                const bool up = ((t & (kk >> 3)) == 0);
                const bool keepmin = (up == lower);
#pragma unroll
                for (int e = 0; e < 8; e++) {
                    float o = __shfl_xor_sync(0xFFFFFFFFu, v[e], d);
                    v[e] = keepmin ? fminf(v[e], o) : fmaxf(v[e], o);
                }
            } else {
#pragma unroll
                for (int e = 0; e < 8; e++) {
                    if ((e & j) == 0) {
                        int p = e | j;
                        bool up = ((((t << 3) | e) & kk) == 0);
                        float a = v[e], b = v[p];
                        float lo = fminf(a, b), hi = fmaxf(a, b);
                        v[e] = up ? lo : hi;
                        v[p] = up ? hi : lo;
                    }
                }
            }
        }
    }
    __syncthreads();
#pragma unroll
    for (int e = 0; e < 8; e++) sm[t * 8 + e] = v[e];
    __syncthreads();
    if (t == 0) {
        float neg = 0.0f;
#pragma unroll
        for (int s = 0; s < N_S; s++) neg += __expf(2.0f * sm[node_index[s]]);
        atomicAdd(&g_node_loss, (logf(neg) - logf(posSum)) * (1.0f / 4096.0f));
    }
}

// ---------------- finalize ----------------
__global__ void k_finalize(float* __restrict__ out) {
    out[4 * N_NODES + 0] = g_feat_loss;
    out[4 * N_NODES + 1] = g_node_loss;
}

// ---------------- launch ----------------
extern "C" void kernel_launch(void* const* d_in, const int* in_sizes, int n_in,
                              void* d_out, int out_size) {
    const float* seq1      = (const float*)d_in[0];
    const float* seq2      = (const float*)d_in[1];
    const float* adj       = (const float*)d_in[2];
    const float* diff      = (const float*)d_in[3];
    const float* adj_label = (const float*)d_in[4];
    const int*   feat_idx  = (const int*)d_in[5];
    const int*   node_idx  = (const int*)d_in[6];
    const float* b1        = (const float*)d_in[8];
    const float* a1        = (const float*)d_in[9];
    const float* b2        = (const float*)d_in[11];
    const float* a2        = (const float*)d_in[12];
    const float* Wd        = (const float*)d_in[13];
    const float* bd        = (const float*)d_in[14];
    float* out = (float*)d_out;

    static cudaStream_t s1 = nullptr;
    static cudaEvent_t evFork = nullptr, evNode = nullptr;
    if (!s1) {
        cudaStreamCreateWithFlags(&s1, cudaStreamNonBlocking);
        cudaEventCreateWithFlags(&evFork, cudaEventDisableTiming);
        cudaEventCreateWithFlags(&evNode, cudaEventDisableTiming);
        cudaFuncSetAttribute(k_gemm_ftsT, cudaFuncAttributeMaxDynamicSharedMemorySize, SMEM_TOTAL_G);
        cudaFuncSetAttribute(k_gemm_prop, cudaFuncAttributeMaxDynamicSharedMemorySize, SMEM_TOTAL_G);
        cudaFuncSetAttribute(k_gemm_node, cudaFuncAttributeMaxDynamicSharedMemorySize, SMEM_TOTAL_G);
        cudaFuncSetAttribute(k_gemm_G,    cudaFuncAttributeMaxDynamicSharedMemorySize, SMEM_TOTAL_G);
    }

    // ---- critical chain to Z (stream 0): only z=0,1 of prop needed ----
    k_cvt_all<<<(CVT_TOT + 255) / 256, 256>>>(
        (const float4*)seq1, (const float4*)seq2,
        (const float4*)d_in[7], (const float4*)d_in[10]);
    k_gemm_ftsT<<<dim3(32, 4, 4), 256, SMEM_TOTAL_G>>>();
    k_gemm_prop<<<dim3(4, 32, 2), 256, SMEM_TOTAL_G>>>(adj, diff, b1, b2, a1, a2, 0);
    k_compute_Zt<<<128, 256>>>();

    // ---- fork: node path on s1 (depends only on Z, rninv) ----
    cudaEventRecord(evFork, 0);
    cudaStreamWaitEvent(s1, evFork, 0);
    k_gemm_node<<<dim3(32, 32), 256, SMEM_TOTAL_G, s1>>>();
    k_node_sel<<<N_NODES, 512, 0, s1>>>(adj_label, node_idx);
    cudaEventRecord(evNode, s1);

    // ---- stream 0: rest of prop (h3,h4) + feat/ret path, overlapped ----
    k_gemm_prop<<<dim3(4, 32, 2), 256, SMEM_TOTAL_G>>>(adj, diff, b1, b2, a1, a2, 2);
    k_col_reduce<<<dim3(16, 3), 256>>>();
    k_compute_u<<<1, 512>>>(Wd);
    k_ret<<<dim3(512, 4), 256>>>(bd, out);
    k_gemm_G<<<dim3(4, 4, 8), 256, SMEM_TOTAL_G>>>();
    k_feat_loss<<<512, 64>>>(feat_idx);

    // ---- join ----
    cudaStreamWaitEvent(0, evNode, 0);
    k_finalize<<<1, 1>>>(out);
}